// round 6
// baseline (speedup 1.0000x reference)
#include <cuda_runtime.h>
#include <cuda_fp16.h>

// ---------------- problem constants ----------------
#define N_NODES 100000
#define N_EDGES 1600000
#define ET      (N_EDGES + N_NODES)   // edges + self-loops
#define F_IN    128
#define SCAN_TILE 512
#define NTILES  196                   // ceil(100000/512)
#define FULLMASK 0xffffffffu

// ---------------- scratch (no allocs allowed) ----------------
__device__ __align__(16) __half g_h1h[N_NODES * 64];   // fp16 gather operand, layer 1
__device__ __align__(16) __half g_h2h[N_NODES * 64];   // fp16 gather operand, layer 2
__device__ __align__(16) float  g_out1[N_NODES * 64];  // fp32 ELU output (GEMM2 input)
__device__ float g_as1 [N_NODES * 8];
__device__ float g_ad1 [N_NODES * 8];
__device__ float g_as2 [N_NODES];
__device__ float g_ad2 [N_NODES];
__device__ int   g_deg [N_NODES];
__device__ int   g_off [N_NODES + 1];
__device__ int   g_cur [N_NODES];
__device__ int   g_tsum[NTILES];
__device__ int   g_toff[NTILES];
__device__ int   g_csr [ET];

// ================= CSR build =================
__global__ void k_zero_deg() {
    int i = blockIdx.x * 256 + threadIdx.x;
    if (i < N_NODES) g_deg[i] = 0;
}

__global__ void k_hist(const int* __restrict__ ei) {
    int e = blockIdx.x * 256 + threadIdx.x;
    if (e >= ET) return;
    int dst = (e < N_EDGES) ? ei[N_EDGES + e] : (e - N_EDGES);
    atomicAdd(&g_deg[dst], 1);
}

__global__ void k_sums() {
    __shared__ int s[SCAN_TILE];
    int t = threadIdx.x;
    int i = blockIdx.x * SCAN_TILE + t;
    s[t] = (i < N_NODES) ? g_deg[i] : 0;
    __syncthreads();
    for (int st = SCAN_TILE / 2; st > 0; st >>= 1) {
        if (t < st) s[t] += s[t + st];
        __syncthreads();
    }
    if (t == 0) g_tsum[blockIdx.x] = s[0];
}

__global__ void k_top() {
    __shared__ int s[256];
    int t = threadIdx.x;
    int v = (t < NTILES) ? g_tsum[t] : 0;
    s[t] = v;
    __syncthreads();
    for (int off = 1; off < 256; off <<= 1) {
        int u = (t >= off) ? s[t - off] : 0;
        __syncthreads();
        s[t] += u;
        __syncthreads();
    }
    if (t < NTILES) g_toff[t] = s[t] - v;
}

__global__ void k_fin() {
    __shared__ int s[SCAN_TILE];
    int t = threadIdx.x;
    int i = blockIdx.x * SCAN_TILE + t;
    int v = (i < N_NODES) ? g_deg[i] : 0;
    s[t] = v;
    __syncthreads();
    for (int off = 1; off < SCAN_TILE; off <<= 1) {
        int u = (t >= off) ? s[t - off] : 0;
        __syncthreads();
        s[t] += u;
        __syncthreads();
    }
    int excl = s[t] - v + g_toff[blockIdx.x];
    if (i < N_NODES) { g_off[i] = excl; g_cur[i] = excl; }
    if (i == 0) g_off[N_NODES] = ET;
}

__global__ void k_scatter(const int* __restrict__ ei) {
    int e = blockIdx.x * 256 + threadIdx.x;
    if (e >= ET) return;
    int src, dst;
    if (e < N_EDGES) { src = ei[e]; dst = ei[N_EDGES + e]; }
    else             { src = dst = e - N_EDGES; }
    int pos = atomicAdd(&g_cur[dst], 1);
    g_csr[pos] = src;
}

// ================= GEMM 1: h1 = x @ W1 (fp16 out), per-head alpha dots =================
#define FMA4(acc, xv, wv) \
    acc.x = fmaf((xv), (wv).x, acc.x); acc.y = fmaf((xv), (wv).y, acc.y); \
    acc.z = fmaf((xv), (wv).z, acc.z); acc.w = fmaf((xv), (wv).w, acc.w);

__global__ __launch_bounds__(256) void k_gemm1(
        const float* __restrict__ x, const float* __restrict__ W1,
        const float* __restrict__ a_s, const float* __restrict__ a_d) {
    __shared__ float sW[64 * 64];
    __shared__ float sX[32 * 132];
    __shared__ float sas[64], sad[64];
    __shared__ float sAS[32 * 8], sAD[32 * 8];
    int t = threadIdx.x;
    int node0 = blockIdx.x * 32;
    if (t < 64) { sas[t] = a_s[t]; sad[t] = a_d[t]; }
    sAS[t] = 0.f; sAD[t] = 0.f;
#pragma unroll
    for (int i = 0; i < 16; i++) {
        int idx = t + 256 * i;
        int n = idx >> 7, k = idx & 127;
        sX[n * 132 + k] = x[(long long)(node0 + n) * F_IN + k];
    }
    int ng = t >> 4, cg = t & 15;
    int nA = ng * 2, nB = nA + 1;
    int c0 = cg * 4;
    float4 a0 = make_float4(0.f, 0.f, 0.f, 0.f);
    float4 a1 = make_float4(0.f, 0.f, 0.f, 0.f);

    for (int kc = 0; kc < 128; kc += 64) {
        __syncthreads();
#pragma unroll
        for (int i = 0; i < 16; i++) {
            int idx = t + 256 * i;
            int k = idx >> 6, c = idx & 63;
            sW[idx] = W1[(kc + k) * 64 + c];
        }
        __syncthreads();
#pragma unroll
        for (int k4 = 0; k4 < 64; k4 += 4) {
            float4 xa = *(const float4*)&sX[nA * 132 + kc + k4];
            float4 xb = *(const float4*)&sX[nB * 132 + kc + k4];
            float4 w0 = *(const float4*)&sW[(k4 + 0) * 64 + c0];
            float4 w1 = *(const float4*)&sW[(k4 + 1) * 64 + c0];
            float4 w2 = *(const float4*)&sW[(k4 + 2) * 64 + c0];
            float4 w3 = *(const float4*)&sW[(k4 + 3) * 64 + c0];
            FMA4(a0, xa.x, w0); FMA4(a0, xa.y, w1); FMA4(a0, xa.z, w2); FMA4(a0, xa.w, w3);
            FMA4(a1, xb.x, w0); FMA4(a1, xb.y, w1); FMA4(a1, xb.z, w2); FMA4(a1, xb.w, w3);
        }
    }
    int head = cg >> 1;
    // fp16 store: 4 channels = 8 bytes (uint2)
    {
        __half2 p0 = __floats2half2_rn(a0.x, a0.y);
        __half2 p1 = __floats2half2_rn(a0.z, a0.w);
        uint2 u; u.x = *(unsigned*)&p0; u.y = *(unsigned*)&p1;
        *(uint2*)&g_h1h[(long long)(node0 + nA) * 64 + c0] = u;
        p0 = __floats2half2_rn(a1.x, a1.y);
        p1 = __floats2half2_rn(a1.z, a1.w);
        u.x = *(unsigned*)&p0; u.y = *(unsigned*)&p1;
        *(uint2*)&g_h1h[(long long)(node0 + nB) * 64 + c0] = u;
    }
    float psA = a0.x * sas[c0] + a0.y * sas[c0 + 1] + a0.z * sas[c0 + 2] + a0.w * sas[c0 + 3];
    float pdA = a0.x * sad[c0] + a0.y * sad[c0 + 1] + a0.z * sad[c0 + 2] + a0.w * sad[c0 + 3];
    float psB = a1.x * sas[c0] + a1.y * sas[c0 + 1] + a1.z * sas[c0 + 2] + a1.w * sas[c0 + 3];
    float pdB = a1.x * sad[c0] + a1.y * sad[c0 + 1] + a1.z * sad[c0 + 2] + a1.w * sad[c0 + 3];
    atomicAdd(&sAS[nA * 8 + head], psA); atomicAdd(&sAD[nA * 8 + head], pdA);
    atomicAdd(&sAS[nB * 8 + head], psB); atomicAdd(&sAD[nB * 8 + head], pdB);
    __syncthreads();
    g_as1[node0 * 8 + t] = sAS[t];
    g_ad1[node0 * 8 + t] = sAD[t];
}

// ================= agg layer 1: warp/node, 4 edges/step, 8 lanes/edge (1 head/lane) =================
__global__ __launch_bounds__(256) void k_agg1(const float* __restrict__ b1) {
    int warp = threadIdx.x >> 5, lane = threadIdx.x & 31;
    int node = blockIdx.x * 8 + warp;
    int qw = lane >> 3;                    // which edge of the quad
    int l8 = lane & 7;                     // head index == channel octet
    int c0 = l8 * 8;
    float adv = g_ad1[node * 8 + l8];
    int beg = g_off[node];
    int deg = g_off[node + 1] - beg;
    float acc[8] = {0.f, 0.f, 0.f, 0.f, 0.f, 0.f, 0.f, 0.f};
    float den = 0.f;
    for (int base = 0; base < deg; base += 32) {
        int idx = base + lane;
        int sreg = (idx < deg) ? g_csr[beg + idx] : 0;
        int cnt = min(32, deg - base);
#pragma unroll 4
        for (int i = 0; i < cnt; i += 4) {
            int pair = i + qw;
            int s = __shfl_sync(FULLMASK, sreg, pair & 31);
            if (pair < cnt) {
                float ev = __ldg(&g_as1[s * 8 + l8]) + adv;
                ev = ev > 0.f ? ev : 0.2f * ev;
                float p = __expf(ev);
                uint4 hv = *(const uint4*)&g_h1h[(long long)s * 64 + c0];
                __half2* hp = (__half2*)&hv;
                float2 f;
                f = __half22float2(hp[0]); acc[0] = fmaf(p, f.x, acc[0]); acc[1] = fmaf(p, f.y, acc[1]);
                f = __half22float2(hp[1]); acc[2] = fmaf(p, f.x, acc[2]); acc[3] = fmaf(p, f.y, acc[3]);
                f = __half22float2(hp[2]); acc[4] = fmaf(p, f.x, acc[4]); acc[5] = fmaf(p, f.y, acc[5]);
                f = __half22float2(hp[3]); acc[6] = fmaf(p, f.x, acc[6]); acc[7] = fmaf(p, f.y, acc[7]);
                den += p;
            }
        }
    }
    // merge the 4 quad edge-streams (lanes with equal l8 hold the same head)
#pragma unroll
    for (int j = 0; j < 8; j++) {
        acc[j] += __shfl_xor_sync(FULLMASK, acc[j], 8);
        acc[j] += __shfl_xor_sync(FULLMASK, acc[j], 16);
    }
    den += __shfl_xor_sync(FULLMASK, den, 8);
    den += __shfl_xor_sync(FULLMASK, den, 16);
    if (qw == 0) {
        float inv = 1.f / (den + 1e-16f);
        float4 b_lo = *(const float4*)&b1[c0];
        float4 b_hi = *(const float4*)&b1[c0 + 4];
        float4 o0, o1;
        o0.x = acc[0] * inv + b_lo.x; o0.y = acc[1] * inv + b_lo.y;
        o0.z = acc[2] * inv + b_lo.z; o0.w = acc[3] * inv + b_lo.w;
        o1.x = acc[4] * inv + b_hi.x; o1.y = acc[5] * inv + b_hi.y;
        o1.z = acc[6] * inv + b_hi.z; o1.w = acc[7] * inv + b_hi.w;
        o0.x = o0.x > 0.f ? o0.x : expm1f(o0.x);
        o0.y = o0.y > 0.f ? o0.y : expm1f(o0.y);
        o0.z = o0.z > 0.f ? o0.z : expm1f(o0.z);
        o0.w = o0.w > 0.f ? o0.w : expm1f(o0.w);
        o1.x = o1.x > 0.f ? o1.x : expm1f(o1.x);
        o1.y = o1.y > 0.f ? o1.y : expm1f(o1.y);
        o1.z = o1.z > 0.f ? o1.z : expm1f(o1.z);
        o1.w = o1.w > 0.f ? o1.w : expm1f(o1.w);
        *(float4*)&g_out1[(long long)node * 64 + c0]     = o0;
        *(float4*)&g_out1[(long long)node * 64 + c0 + 4] = o1;
    }
}

// ================= GEMM 2: h2 = out1 @ W2 (fp16 out), alpha2 dots =================
__global__ __launch_bounds__(256) void k_gemm2(
        const float* __restrict__ W2,
        const float* __restrict__ a_s, const float* __restrict__ a_d) {
    __shared__ float sW[64 * 64];
    __shared__ float sX[32 * 68];
    __shared__ float sas[64], sad[64];
    __shared__ float sAS[32], sAD[32];
    int t = threadIdx.x;
    int node0 = blockIdx.x * 32;
    if (t < 64) { sas[t] = a_s[t]; sad[t] = a_d[t]; }
    if (t < 32) { sAS[t] = 0.f; sAD[t] = 0.f; }
#pragma unroll
    for (int i = 0; i < 8; i++) {
        int idx = t + 256 * i;
        int n = idx >> 6, k = idx & 63;
        sX[n * 68 + k] = g_out1[(long long)(node0 + n) * 64 + k];
    }
#pragma unroll
    for (int i = 0; i < 16; i++) {
        int idx = t + 256 * i;
        sW[idx] = W2[idx];
    }
    __syncthreads();
    int ng = t >> 4, cg = t & 15;
    int nA = ng * 2, nB = nA + 1;
    int c0 = cg * 4;
    float4 a0 = make_float4(0.f, 0.f, 0.f, 0.f);
    float4 a1 = make_float4(0.f, 0.f, 0.f, 0.f);
#pragma unroll
    for (int k4 = 0; k4 < 64; k4 += 4) {
        float4 xa = *(const float4*)&sX[nA * 68 + k4];
        float4 xb = *(const float4*)&sX[nB * 68 + k4];
        float4 w0 = *(const float4*)&sW[(k4 + 0) * 64 + c0];
        float4 w1 = *(const float4*)&sW[(k4 + 1) * 64 + c0];
        float4 w2 = *(const float4*)&sW[(k4 + 2) * 64 + c0];
        float4 w3 = *(const float4*)&sW[(k4 + 3) * 64 + c0];
        FMA4(a0, xa.x, w0); FMA4(a0, xa.y, w1); FMA4(a0, xa.z, w2); FMA4(a0, xa.w, w3);
        FMA4(a1, xb.x, w0); FMA4(a1, xb.y, w1); FMA4(a1, xb.z, w2); FMA4(a1, xb.w, w3);
    }
    {
        __half2 p0 = __floats2half2_rn(a0.x, a0.y);
        __half2 p1 = __floats2half2_rn(a0.z, a0.w);
        uint2 u; u.x = *(unsigned*)&p0; u.y = *(unsigned*)&p1;
        *(uint2*)&g_h2h[(long long)(node0 + nA) * 64 + c0] = u;
        p0 = __floats2half2_rn(a1.x, a1.y);
        p1 = __floats2half2_rn(a1.z, a1.w);
        u.x = *(unsigned*)&p0; u.y = *(unsigned*)&p1;
        *(uint2*)&g_h2h[(long long)(node0 + nB) * 64 + c0] = u;
    }
    float psA = a0.x * sas[c0] + a0.y * sas[c0 + 1] + a0.z * sas[c0 + 2] + a0.w * sas[c0 + 3];
    float pdA = a0.x * sad[c0] + a0.y * sad[c0 + 1] + a0.z * sad[c0 + 2] + a0.w * sad[c0 + 3];
    float psB = a1.x * sas[c0] + a1.y * sas[c0 + 1] + a1.z * sas[c0 + 2] + a1.w * sas[c0 + 3];
    float pdB = a1.x * sad[c0] + a1.y * sad[c0 + 1] + a1.z * sad[c0 + 2] + a1.w * sad[c0 + 3];
    atomicAdd(&sAS[nA], psA); atomicAdd(&sAD[nA], pdA);
    atomicAdd(&sAS[nB], psB); atomicAdd(&sAD[nB], pdB);
    __syncthreads();
    if (t < 32) { g_as2[node0 + t] = sAS[t]; g_ad2[node0 + t] = sAD[t]; }
}

// ================= agg layer 2 + bias + log_softmax =================
__global__ __launch_bounds__(256) void k_agg2(const float* __restrict__ b2,
                                              float* __restrict__ out) {
    int warp = threadIdx.x >> 5, lane = threadIdx.x & 31;
    int node = blockIdx.x * 8 + warp;
    int qw = lane >> 3;
    int l8 = lane & 7;
    int c0 = l8 * 8;
    float adv = g_ad2[node];
    int beg = g_off[node];
    int deg = g_off[node + 1] - beg;
    float acc[8] = {0.f, 0.f, 0.f, 0.f, 0.f, 0.f, 0.f, 0.f};
    float den = 0.f;
    for (int base = 0; base < deg; base += 32) {
        int idx = base + lane;
        int sreg = (idx < deg) ? g_csr[beg + idx] : 0;
        int cnt = min(32, deg - base);
#pragma unroll 4
        for (int i = 0; i < cnt; i += 4) {
            int pair = i + qw;
            int s = __shfl_sync(FULLMASK, sreg, pair & 31);
            if (pair < cnt) {
                float ev = __ldg(&g_as2[s]) + adv;   // broadcast within quad
                ev = ev > 0.f ? ev : 0.2f * ev;
                float p = __expf(ev);
                uint4 hv = *(const uint4*)&g_h2h[(long long)s * 64 + c0];
                __half2* hp = (__half2*)&hv;
                float2 f;
                f = __half22float2(hp[0]); acc[0] = fmaf(p, f.x, acc[0]); acc[1] = fmaf(p, f.y, acc[1]);
                f = __half22float2(hp[1]); acc[2] = fmaf(p, f.x, acc[2]); acc[3] = fmaf(p, f.y, acc[3]);
                f = __half22float2(hp[2]); acc[4] = fmaf(p, f.x, acc[4]); acc[5] = fmaf(p, f.y, acc[5]);
                f = __half22float2(hp[3]); acc[6] = fmaf(p, f.x, acc[6]); acc[7] = fmaf(p, f.y, acc[7]);
                den += p;
            }
        }
    }
#pragma unroll
    for (int j = 0; j < 8; j++) {
        acc[j] += __shfl_xor_sync(FULLMASK, acc[j], 8);
        acc[j] += __shfl_xor_sync(FULLMASK, acc[j], 16);
    }
    den += __shfl_xor_sync(FULLMASK, den, 8);
    den += __shfl_xor_sync(FULLMASK, den, 16);
    float inv = 1.f / (den + 1e-16f);
    float y[8];
#pragma unroll
    for (int j = 0; j < 8; j++) y[j] = acc[j] * inv + b2[c0 + j];
    // log_softmax over 64 channels: reduce over the 8 l8-lanes (redundant in all quads)
    float m = y[0];
#pragma unroll
    for (int j = 1; j < 8; j++) m = fmaxf(m, y[j]);
#pragma unroll
    for (int off = 1; off < 8; off <<= 1)
        m = fmaxf(m, __shfl_xor_sync(FULLMASK, m, off));
    float es = 0.f;
#pragma unroll
    for (int j = 0; j < 8; j++) es += __expf(y[j] - m);
#pragma unroll
    for (int off = 1; off < 8; off <<= 1)
        es += __shfl_xor_sync(FULLMASK, es, off);
    float ls = m + __logf(es);
    if (qw == 0) {
        float4 r0, r1;
        r0.x = y[0] - ls; r0.y = y[1] - ls; r0.z = y[2] - ls; r0.w = y[3] - ls;
        r1.x = y[4] - ls; r1.y = y[5] - ls; r1.z = y[6] - ls; r1.w = y[7] - ls;
        *(float4*)&out[(long long)node * 64 + c0]     = r0;
        *(float4*)&out[(long long)node * 64 + c0 + 4] = r1;
    }
}

// ---------------- launcher ----------------
extern "C" void kernel_launch(void* const* d_in, const int* in_sizes, int n_in,
                              void* d_out, int out_size) {
    const float* x   = (const float*)d_in[0];
    const int*   ei  = (const int*)  d_in[1];
    const float* W1  = (const float*)d_in[2];
    const float* as1 = (const float*)d_in[3];
    const float* ad1 = (const float*)d_in[4];
    const float* b1  = (const float*)d_in[5];
    const float* W2  = (const float*)d_in[6];
    const float* as2 = (const float*)d_in[7];
    const float* ad2 = (const float*)d_in[8];
    const float* b2  = (const float*)d_in[9];
    float* out = (float*)d_out;

    int eblocks = (ET + 255) / 256;

    k_zero_deg<<<(N_NODES + 255) / 256, 256>>>();
    k_hist<<<eblocks, 256>>>(ei);
    k_sums<<<NTILES, SCAN_TILE>>>();
    k_top<<<1, 256>>>();
    k_fin<<<NTILES, SCAN_TILE>>>();
    k_scatter<<<eblocks, 256>>>(ei);

    k_gemm1<<<N_NODES / 32, 256>>>(x, W1, as1, ad1);
    k_agg1<<<N_NODES / 8, 256>>>(b1);
    k_gemm2<<<N_NODES / 32, 256>>>(W2, as2, ad2);
    k_agg2<<<N_NODES / 8, 256>>>(b2, out);
}